// round 1
// baseline (speedup 1.0000x reference)
#include <cuda_runtime.h>
#include <math.h>

#define BB    8
#define CIN   256
#define COUT  128
#define HH    64
#define WW    64
#define HWSZ  (HH*WW)
#define OHH   128
#define OWW   128
#define OHW   (OHH*OWW)

// ---------------- device scratch (no allocations allowed) ----------------
__device__ float g_om [BB*27*HWSZ];                 // offset-conv output [B,27,64,64]
__device__ float g_y1 [BB*COUT*HWSZ];               // dcn output / bn1 in-place
__device__ float g_Wt1[CIN*9*COUT];                 // dcn weight, k-major [2304][128]
__device__ float g_Wt2[4*COUT*4*COUT];              // deconv weight per parity [4][512][128]
__device__ float g_st1[2*COUT];                     // bn1 mean / invstd
__device__ float g_st2[2*COUT];                     // bn2 mean / invstd

// ---------------- weight pre-transpose ----------------
__global__ void prep_kernel(const float* __restrict__ dcn_w, const float* __restrict__ up_w) {
    int n1 = CIN*9*COUT;                 // Wt1[(c*9+k)*128+o] = dcn_w[o][c*9+k]
    for (int idx = blockIdx.x*blockDim.x + threadIdx.x; idx < n1; idx += gridDim.x*blockDim.x) {
        int kk = idx / COUT;
        int o  = idx - kk*COUT;
        g_Wt1[idx] = dcn_w[o*(CIN*9) + kk];
    }
    int n2 = 4*512*COUT;                 // Wt2[pc][c*4+th*2+tw][o] = up_w[c][o][ph+2th][pw+2tw]
    for (int idx = blockIdx.x*blockDim.x + threadIdx.x; idx < n2; idx += gridDim.x*blockDim.x) {
        int o  = idx & (COUT-1);
        int kk = (idx >> 7) & 511;
        int pc = idx >> 16;              // 128*512 = 65536
        int c  = kk >> 2;
        int th = (kk >> 1) & 1;
        int tw = kk & 1;
        int ph = pc >> 1, pw = pc & 1;
        int kh = ph + 2*th, kw = pw + 2*tw;
        g_Wt2[idx] = up_w[((c*COUT + o)*4 + kh)*4 + kw];
    }
}

// ---------------- offset conv: x[B,256,64,64] -> g_om[B,27,64,64] ----------------
__global__ __launch_bounds__(256) void offconv_kernel(const float* __restrict__ x,
                                                      const float* __restrict__ off_w,
                                                      const float* __restrict__ off_b) {
    __shared__ float xs[8][3][66];
    __shared__ float ws[2048];          // 8 cin * 243 (+pad)
    int h = blockIdx.x, b = blockIdx.y;
    int tid = threadIdx.x;
    int w  = tid & 63;
    int ty = tid >> 6;                  // 0..3 -> oc = ty + 4*i
    float acc[7];
#pragma unroll
    for (int i = 0; i < 7; i++) acc[i] = 0.f;

    for (int c0 = 0; c0 < CIN; c0 += 8) {
        for (int idx = tid; idx < 8*198; idx += 256) {
            int cl = idx / 198; int rem = idx - cl*198;
            int r = rem / 66;   int j = rem - r*66;
            int hh = h - 1 + r; int wwp = j - 1;
            float v = 0.f;
            if (hh >= 0 && hh < HH && wwp >= 0 && wwp < WW)
                v = x[((b*CIN + c0 + cl)*HH + hh)*WW + wwp];
            xs[cl][r][j] = v;
        }
        for (int idx = tid; idx < 8*243; idx += 256) {
            int cl = idx / 243; int t = idx - cl*243;   // t = oc*9+k
            ws[cl*243 + t] = off_w[((t/9)*CIN + c0 + cl)*9 + (t % 9)];
        }
        __syncthreads();
#pragma unroll
        for (int cl = 0; cl < 8; cl++) {
#pragma unroll
            for (int k2 = 0; k2 < 9; k2++) {
                float xv = xs[cl][k2/3][w + (k2 % 3)];
#pragma unroll
                for (int i = 0; i < 7; i++) {
                    int oc = ty + 4*i;                   // may exceed 26 only for unstored lane
                    acc[i] += ws[cl*243 + oc*9 + k2] * xv;
                }
            }
        }
        __syncthreads();
    }
#pragma unroll
    for (int i = 0; i < 7; i++) {
        int oc = ty + 4*i;
        if (oc < 27)
            g_om[((b*27 + oc)*HH + h)*WW + w] = acc[i] + off_b[oc];
    }
}

// ---------------- modulated deformable conv: GEMM 128 x 32px, K=2304 ----------------
__global__ __launch_bounds__(256) void mdcn_kernel(const float* __restrict__ x,
                                                   const float* __restrict__ dcn_b) {
    __shared__ int   si[4][288];
    __shared__ float swt[4][288];
    __shared__ float Wsh[36*128];
    __shared__ float colsh[36*32];

    int tile = blockIdx.x;              // 0..1 -> w0
    int h = blockIdx.y, b = blockIdx.z;
    int w0 = tile * 32;
    int tid = threadIdx.x;

    // sampling precompute: 9 taps x 32 px
    for (int s = tid; s < 288; s += 256) {
        int k2 = s >> 5, px = s & 31;
        int w = w0 + px;
        const float* omb = g_om + (size_t)b*27*HWSZ + h*WW + w;
        float dy = omb[(2*k2)    * HWSZ];
        float dx = omb[(2*k2 + 1)* HWSZ];
        float mv = 1.f / (1.f + expf(-omb[(18 + k2)*HWSZ]));
        float py  = (float)h + (float)(k2/3 - 1) + dy;
        float pxf = (float)w + (float)(k2%3 - 1) + dx;
        float y0f = floorf(py), x0f = floorf(pxf);
        float ly = py - y0f, lx = pxf - x0f;
        int y0 = (int)y0f, x0 = (int)x0f;
        int y1i = y0 + 1, x1i = x0 + 1;
        bool vy0 = (y0  >= 0) && (y0  < HH);
        bool vy1 = (y1i >= 0) && (y1i < HH);
        bool vx0 = (x0  >= 0) && (x0  < WW);
        bool vx1 = (x1i >= 0) && (x1i < WW);
        int cy0 = min(max(y0, 0), HH-1), cy1 = min(max(y1i, 0), HH-1);
        int cx0 = min(max(x0, 0), WW-1), cx1 = min(max(x1i, 0), WW-1);
        si[0][s] = cy0*WW + cx0;  si[1][s] = cy0*WW + cx1;
        si[2][s] = cy1*WW + cx0;  si[3][s] = cy1*WW + cx1;
        swt[0][s] = (1.f - ly)*(1.f - lx) * ((vy0 && vx0) ? mv : 0.f);
        swt[1][s] = (1.f - ly)*lx         * ((vy0 && vx1) ? mv : 0.f);
        swt[2][s] = ly*(1.f - lx)         * ((vy1 && vx0) ? mv : 0.f);
        swt[3][s] = ly*lx                 * ((vy1 && vx1) ? mv : 0.f);
    }
    __syncthreads();

    float acc[4][4] = {};
    int og = tid & 31, pg = tid >> 5;
    const float* xb = x + (size_t)b*CIN*HWSZ;

    for (int c0 = 0; c0 < CIN; c0 += 4) {
        for (int idx = tid; idx < 36*128; idx += 256)
            Wsh[idx] = g_Wt1[(c0*9)*128 + idx];                  // contiguous rows
        for (int idx = tid; idx < 36*32; idx += 256) {
            int kl = idx >> 5, px = idx & 31;
            int cl = kl / 9,  k2 = kl - cl*9;
            const float* xc = xb + (c0 + cl)*HWSZ;
            int s = k2*32 + px;
            colsh[idx] = swt[0][s]*xc[si[0][s]] + swt[1][s]*xc[si[1][s]]
                       + swt[2][s]*xc[si[2][s]] + swt[3][s]*xc[si[3][s]];
        }
        __syncthreads();
#pragma unroll
        for (int kl = 0; kl < 36; kl++) {
            float4 wv = *(const float4*)&Wsh[kl*128 + og*4];
            float4 cv = *(const float4*)&colsh[kl*32 + pg*4];
            float wr[4] = {wv.x, wv.y, wv.z, wv.w};
            float cr[4] = {cv.x, cv.y, cv.z, cv.w};
#pragma unroll
            for (int i = 0; i < 4; i++)
#pragma unroll
                for (int j = 0; j < 4; j++)
                    acc[i][j] += wr[i]*cr[j];
        }
        __syncthreads();
    }
#pragma unroll
    for (int i = 0; i < 4; i++) {
        int o = og*4 + i;
        float bias = dcn_b[o];
#pragma unroll
        for (int j = 0; j < 4; j++) {
            int w = w0 + pg*4 + j;
            g_y1[((b*COUT + o)*HH + h)*WW + w] = acc[i][j] + bias;
        }
    }
}

// ---------------- deconv: GEMM 128 x 32px (same-parity ow), K=512 ----------------
__global__ __launch_bounds__(256) void deconv_kernel(float* __restrict__ out) {
    __shared__ float Wsh[64*128];
    __shared__ float colsh[64*32];

    int t  = blockIdx.x;                 // 0..3
    int oh = blockIdx.y, b = blockIdx.z;
    int par = t & 1, half = t >> 1;
    int ph = (oh + 1) & 1;
    int pw = (par + 1) & 1;
    int pc = ph*2 + pw;
    int IH0 = (oh + 1 - ph) >> 1;
    int tid = threadIdx.x;
    int og = tid & 31, pg = tid >> 5;

    float acc[4][4] = {};
    const float* yb = g_y1 + (size_t)b*COUT*HWSZ;
    const float* Wt2p = g_Wt2 + (size_t)pc*512*128;

    for (int c0 = 0; c0 < COUT; c0 += 16) {
        for (int idx = tid; idx < 64*128; idx += 256)
            Wsh[idx] = Wt2p[(c0*4)*128 + idx];                   // contiguous rows
        for (int idx = tid; idx < 64*32; idx += 256) {
            int kl = idx >> 5, j = idx & 31;
            int cl = kl >> 2, th = (kl >> 1) & 1, tw = kl & 1;
            int ih = IH0 - th;
            int iw = half*32 + j + par - tw;
            float v = 0.f;
            if (ih >= 0 && ih < HH && iw >= 0 && iw < WW)
                v = yb[(c0 + cl)*HWSZ + ih*WW + iw];
            colsh[idx] = v;
        }
        __syncthreads();
#pragma unroll
        for (int kl = 0; kl < 64; kl++) {
            float4 wv = *(const float4*)&Wsh[kl*128 + og*4];
            float4 cv = *(const float4*)&colsh[kl*32 + pg*4];
            float wr[4] = {wv.x, wv.y, wv.z, wv.w};
            float cr[4] = {cv.x, cv.y, cv.z, cv.w};
#pragma unroll
            for (int i = 0; i < 4; i++)
#pragma unroll
                for (int j = 0; j < 4; j++)
                    acc[i][j] += wr[i]*cr[j];
        }
        __syncthreads();
    }
#pragma unroll
    for (int i = 0; i < 4; i++) {
        int o = og*4 + i;
#pragma unroll
        for (int j = 0; j < 4; j++) {
            int ow = par + 2*(half*32 + pg*4 + j);
            out[((size_t)(b*COUT + o)*OHH + oh)*OWW + ow] = acc[i][j];
        }
    }
}

// ---------------- batch-norm stats (training mode, biased variance) ----------------
__global__ __launch_bounds__(256) void bn_stats_kernel(const float* __restrict__ x,
                                                       float* __restrict__ stats, int hw) {
    int c = blockIdx.x;
    float s1 = 0.f, s2 = 0.f;
    for (int bb = 0; bb < BB; bb++) {
        const float* p = x + ((size_t)bb*COUT + c)*hw;
        for (int i = threadIdx.x; i < hw; i += blockDim.x) {
            float v = p[i];
            s1 += v; s2 += v*v;
        }
    }
    __shared__ float r1[32], r2[32];
#pragma unroll
    for (int off = 16; off; off >>= 1) {
        s1 += __shfl_down_sync(~0u, s1, off);
        s2 += __shfl_down_sync(~0u, s2, off);
    }
    int lane = threadIdx.x & 31, wid = threadIdx.x >> 5;
    if (lane == 0) { r1[wid] = s1; r2[wid] = s2; }
    __syncthreads();
    if (wid == 0) {
        s1 = (lane < 8) ? r1[lane] : 0.f;
        s2 = (lane < 8) ? r2[lane] : 0.f;
#pragma unroll
        for (int off = 4; off; off >>= 1) {
            s1 += __shfl_down_sync(~0u, s1, off);
            s2 += __shfl_down_sync(~0u, s2, off);
        }
        if (lane == 0) {
            float n = (float)(BB * hw);
            float mean = s1 / n;
            float var  = s2 / n - mean*mean;
            stats[c]        = mean;
            stats[COUT + c] = rsqrtf(var + 1e-5f);
        }
    }
}

// ---------------- bn apply + relu (in place) ----------------
__global__ __launch_bounds__(256) void bn_apply_kernel(float* __restrict__ x,
                                                       const float* __restrict__ stats,
                                                       const float* __restrict__ g,
                                                       const float* __restrict__ bta, int hw) {
    int bc = blockIdx.y;
    int c = bc & (COUT - 1);
    float sc = stats[COUT + c] * g[c];
    float sh = bta[c] - stats[c] * sc;
    float* p = x + (size_t)bc * hw;
    for (int i = blockIdx.x*blockDim.x + threadIdx.x; i < hw; i += gridDim.x*blockDim.x)
        p[i] = fmaxf(p[i]*sc + sh, 0.f);
}

// ---------------- launch ----------------
extern "C" void kernel_launch(void* const* d_in, const int* in_sizes, int n_in,
                              void* d_out, int out_size) {
    const float* x     = (const float*)d_in[0];
    const float* off_w = (const float*)d_in[1];
    const float* off_b = (const float*)d_in[2];
    const float* dcn_w = (const float*)d_in[3];
    const float* dcn_b = (const float*)d_in[4];
    const float* bn1_g = (const float*)d_in[5];
    const float* bn1_b = (const float*)d_in[6];
    const float* up_w  = (const float*)d_in[7];
    const float* bn2_g = (const float*)d_in[8];
    const float* bn2_b = (const float*)d_in[9];
    float* out = (float*)d_out;

    float *y1p, *st1p, *st2p;
    cudaGetSymbolAddress((void**)&y1p,  g_y1);
    cudaGetSymbolAddress((void**)&st1p, g_st1);
    cudaGetSymbolAddress((void**)&st2p, g_st2);

    prep_kernel<<<256, 256>>>(dcn_w, up_w);
    offconv_kernel<<<dim3(HH, BB), 256>>>(x, off_w, off_b);
    mdcn_kernel<<<dim3(2, HH, BB), 256>>>(x, dcn_b);
    bn_stats_kernel<<<COUT, 256>>>(y1p, st1p, HWSZ);
    bn_apply_kernel<<<dim3(4, BB*COUT), 256>>>(y1p, st1p, bn1_g, bn1_b, HWSZ);
    deconv_kernel<<<dim3(4, OHH, BB), 256>>>(out);
    bn_stats_kernel<<<COUT, 256>>>(out, st2p, OHW);
    bn_apply_kernel<<<dim3(8, BB*COUT), 256>>>(out, st2p, bn2_g, bn2_b, OHW);
}